// round 5
// baseline (speedup 1.0000x reference)
#include <cuda_runtime.h>

// Shapes fixed by dataset: x:(64,16,128,2), log_delay:(256,1), log_weight scalar,
// noise:(16,128,256,2), out:(64,16,128,256) fp32.
#define T_DIM 64
#define N_DIM 16
#define C_DIM 128
#define D_DIM 256

// One 128-thread block per (n,c) pair. Each thread owns 2 consecutive d.
// Output stores are write-through (__stwt): the 134MB output is write-once
// dead data; leaving it dirty in L2 forces an eviction per store line on the
// NEXT replay (steady-state double handling in LTS). Write-through keeps L2
// lines clean so replays don't pay the dirty-eviction tax.
__global__ __launch_bounds__(128) void jeffress_kernel(
    const float* __restrict__ x,
    const float* __restrict__ log_delay,
    const float* __restrict__ log_weight,
    const float* __restrict__ noise,
    float* __restrict__ out)
{
    // x duplicated along t so (t - rd) mod 64 becomes base + t.
    __shared__ float xs[2][128];
    __shared__ int maxd_sh[2];

    const int tid = threadIdx.x;       // 0..127
    const int nc  = blockIdx.x;        // 0..2047
    const int n   = nc >> 7;
    const int c   = nc & 127;
    const float w = expf(__ldg(log_weight));

    // ---- load x[t] (both streams), pre-scaled by w, duplicated for wrap
    if (tid < 64) {
        const float2 v2 = *reinterpret_cast<const float2*>(
            x + (((size_t)tid * N_DIM + n) * C_DIM + c) * 2);
        float v0 = w * v2.x;
        float v1 = w * v2.y;
        xs[0][tid]      = v0;  xs[0][tid + 64] = v0;
        xs[1][tid]      = v1;  xs[1][tid + 64] = v1;
    }
    __syncthreads();

    // ---- argmax over t per stream j (warps 0 and 1), first-occurrence wins
    if (tid < 64) {
        const int wj   = tid >> 5;
        const int lane = tid & 31;
        float v1 = xs[wj][lane];
        float v2 = xs[wj][lane + 32];
        float v; int idx;
        if (v2 > v1) { v = v2; idx = lane + 32; } else { v = v1; idx = lane; }
        #pragma unroll
        for (int o = 16; o > 0; o >>= 1) {
            float ov = __shfl_xor_sync(0xffffffffu, v, o);
            int   oi = __shfl_xor_sync(0xffffffffu, idx, o);
            if (ov > v || (ov == v && oi < idx)) { v = ov; idx = oi; }
        }
        if (lane == 0) maxd_sh[wj] = (T_DIM - 1) - idx;
    }
    __syncthreads();

    const int d0  = tid << 1;          // 2 consecutive d per thread
    const int md0 = maxd_sh[0];
    const int md1 = maxd_sh[1];

    // noise[(nc*256 + d)*2 + j]: 4 consecutive floats -> one float4 load,
    // streaming (read-once, don't pollute L2)
    const float4 nz = __ldcs(reinterpret_cast<const float4*>(
        noise + ((size_t)nc * D_DIM + d0) * 2));
    float nz0[2] = {nz.x, nz.z};   // j = 0
    float nz1[2] = {nz.y, nz.w};   // j = 1

    // ---- per-(d, stream) delays -> base pointers into the duplicated array
    const float* b0[2];
    const float* b1[2];
    #pragma unroll
    for (int i = 0; i < 2; i++) {
        int d = d0 + i;
        float s0 = 64.0f * expf(__ldg(log_delay + d));
        float s1 = 64.0f * expf(__ldg(log_delay + (D_DIM - 1 - d)));  // flip
        float f0 = floorf(s0), f1 = floorf(s1);
        int r0 = (int)f0 + ((nz0[i] < (s0 - f0)) ? 1 : 0);
        int r1 = (int)f1 + ((nz1[i] < (s1 - f1)) ? 1 : 0);
        int rd0 = min(r0, md0);
        int rd1 = min(r1, md1);
        b0[i] = &xs[0][64 - rd0];      // b[t] == x[(t - rd) mod 64]
        b1[i] = &xs[1][64 - rd1];
    }

    // ---- main scan: y_t = 0.5*y_{t-1} + x_shifted, out = y(j=0)+y(j=1)
    float y0[2] = {0.f, 0.f};
    float y1[2] = {0.f, 0.f};
    float2* outp = reinterpret_cast<float2*>(out + (size_t)nc * D_DIM + d0);
    const size_t tstride2 = (size_t)N_DIM * C_DIM * D_DIM / 2;

    #pragma unroll 8
    for (int t = 0; t < T_DIM; t++) {
        float2 v;
        #pragma unroll
        for (int i = 0; i < 2; i++) {
            y0[i] = y0[i] * 0.5f + b0[i][t];
            y1[i] = y1[i] * 0.5f + b1[i][t];
        }
        v.x = y0[0] + y1[0];
        v.y = y0[1] + y1[1];
        __stwt(outp, v);               // write-through: no dirty L2 lines
        outp += tstride2;
    }
}

extern "C" void kernel_launch(void* const* d_in, const int* in_sizes, int n_in,
                              void* d_out, int out_size) {
    const float* x          = (const float*)d_in[0];
    const float* log_delay  = (const float*)d_in[1];
    const float* log_weight = (const float*)d_in[2];
    const float* noise      = (const float*)d_in[3];
    float* out = (float*)d_out;

    jeffress_kernel<<<N_DIM * C_DIM, 128>>>(x, log_delay, log_weight, noise, out);
}

// round 6
// speedup vs baseline: 1.0748x; 1.0748x over previous
#include <cuda_runtime.h>

// Shapes fixed by dataset: x:(64,16,128,2), log_delay:(256,1), log_weight scalar,
// noise:(16,128,256,2), out:(64,16,128,256) fp32.
#define T_DIM 64
#define N_DIM 16
#define C_DIM 128
#define D_DIM 256

// One 64-thread block per (n,c) pair (best measured config). Each thread owns
// 4 consecutive d -> float4 stores (512B contiguous per warp per t).
// The kernel is pinned at the L2 write-port floor (~3150 B/cyc for 134MB of
// output); SM-side structure is irrelevant. Only remaining lever: keep the
// read-once 9MB noise stream out of L2 (__ldcs) so the output write stream
// keeps maximal L2 residency across graph replays.
__global__ __launch_bounds__(64) void jeffress_kernel(
    const float* __restrict__ x,
    const float* __restrict__ log_delay,
    const float* __restrict__ log_weight,
    const float* __restrict__ noise,
    float* __restrict__ out)
{
    // x duplicated along t so (t - rd) mod 64 becomes base + t.
    __shared__ float xs[2][128];
    __shared__ int maxd_sh[2];

    const int tid = threadIdx.x;       // 0..63
    const int nc  = blockIdx.x;        // 0..2047
    const int n   = nc >> 7;
    const int c   = nc & 127;
    const float w = expf(__ldg(log_weight));

    // ---- load x[t=tid] (both streams), pre-scaled by w, duplicated
    {
        const float2 v2 = *reinterpret_cast<const float2*>(
            x + (((size_t)tid * N_DIM + n) * C_DIM + c) * 2);
        float v0 = w * v2.x;
        float v1 = w * v2.y;
        xs[0][tid]      = v0;  xs[0][tid + 64] = v0;
        xs[1][tid]      = v1;  xs[1][tid + 64] = v1;
    }
    __syncthreads();

    // ---- argmax over t per stream j (first-occurrence semantics)
    {
        const int wj   = tid >> 5;
        const int lane = tid & 31;
        float v1 = xs[wj][lane];
        float v2 = xs[wj][lane + 32];
        float v; int idx;
        if (v2 > v1) { v = v2; idx = lane + 32; } else { v = v1; idx = lane; }
        #pragma unroll
        for (int o = 16; o > 0; o >>= 1) {
            float ov = __shfl_xor_sync(0xffffffffu, v, o);
            int   oi = __shfl_xor_sync(0xffffffffu, idx, o);
            if (ov > v || (ov == v && oi < idx)) { v = ov; idx = oi; }
        }
        if (lane == 0) maxd_sh[wj] = (T_DIM - 1) - idx;
    }
    __syncthreads();

    const int d0  = tid << 2;          // 4 consecutive d per thread
    const int md0 = maxd_sh[0];
    const int md1 = maxd_sh[1];

    // noise[(nc*256 + d)*2 + j]: 8 consecutive floats -> two float4 loads,
    // streaming (read-once; don't evict the resident output stream from L2)
    const float4* nzp = reinterpret_cast<const float4*>(
        noise + ((size_t)nc * D_DIM + d0) * 2);
    float4 nzA = __ldcs(nzp);
    float4 nzB = __ldcs(nzp + 1);
    float nz0[4] = {nzA.x, nzA.z, nzB.x, nzB.z};   // j = 0
    float nz1[4] = {nzA.y, nzA.w, nzB.y, nzB.w};   // j = 1

    // ---- per-(d, stream) delays -> base pointers into the duplicated array
    const float* b0[4];
    const float* b1[4];
    #pragma unroll
    for (int i = 0; i < 4; i++) {
        int d = d0 + i;
        float s0 = 64.0f * expf(__ldg(log_delay + d));
        float s1 = 64.0f * expf(__ldg(log_delay + (D_DIM - 1 - d)));  // flip
        float f0 = floorf(s0), f1 = floorf(s1);
        int r0 = (int)f0 + ((nz0[i] < (s0 - f0)) ? 1 : 0);
        int r1 = (int)f1 + ((nz1[i] < (s1 - f1)) ? 1 : 0);
        int rd0 = min(r0, md0);
        int rd1 = min(r1, md1);
        b0[i] = &xs[0][64 - rd0];      // b[t] == x[(t - rd) mod 64]
        b1[i] = &xs[1][64 - rd1];
    }

    // ---- main scan: y_t = 0.5*y_{t-1} + x_shifted, out = y(j=0)+y(j=1)
    float y0[4] = {0.f, 0.f, 0.f, 0.f};
    float y1[4] = {0.f, 0.f, 0.f, 0.f};
    float4* outp = reinterpret_cast<float4*>(out + (size_t)nc * D_DIM + d0);
    const size_t tstride4 = (size_t)N_DIM * C_DIM * D_DIM / 4;

    #pragma unroll 8
    for (int t = 0; t < T_DIM; t++) {
        float4 v;
        #pragma unroll
        for (int i = 0; i < 4; i++) {
            y0[i] = y0[i] * 0.5f + b0[i][t];
            y1[i] = y1[i] * 0.5f + b1[i][t];
        }
        v.x = y0[0] + y1[0];
        v.y = y0[1] + y1[1];
        v.z = y0[2] + y1[2];
        v.w = y0[3] + y1[3];
        *outp = v;                     // default write-back (best measured)
        outp += tstride4;
    }
}

extern "C" void kernel_launch(void* const* d_in, const int* in_sizes, int n_in,
                              void* d_out, int out_size) {
    const float* x          = (const float*)d_in[0];
    const float* log_delay  = (const float*)d_in[1];
    const float* log_weight = (const float*)d_in[2];
    const float* noise      = (const float*)d_in[3];
    float* out = (float*)d_out;

    jeffress_kernel<<<N_DIM * C_DIM, 64>>>(x, log_delay, log_weight, noise, out);
}